// round 6
// baseline (speedup 1.0000x reference)
#include <cuda_runtime.h>
#include <math.h>
#include <stdint.h>

#define NROWS 8192      // B*T
#define HD    640
#define NP    230
#define NM    96
#define TM    64        // rows per CTA
#define KC    32        // k per chunk
#define NCHUNK (HD / KC)  // 20
#define STAGES 3
#define A_PAD 36
#define P_PAD 258
#define M_PAD 97
#define MAXINV 32

#define A_BYTES 9216    // 64*36*4
#define B_BYTES 32768   // 8192 floats

// ---- smem byte offsets ----
#define SM_A0    0                        // 3 x 9216  = 27648
#define SM_B0    27648                    // 3 x 32768 = 98304 -> 125952
// epilogue aliases GEMM region [0,125952):
#define SM_PHONE 0                        // 64*258*4 = 66048
#define SM_PH    66048                    // 64*97*4  = 24832 -> 90880
// persistent tables (beyond GEMM buffers):
#define SM_TBL   125952                   // icnt 96*4 -> 126336
#define SM_ILIST 126336                   // 96*32    -> 129408
#define SM_MAXV  129408                   // 64*4
#define SM_LSEV  129664                   // 64*4
#define SM_TOTAL 129920

__device__ float         g_Bp[NCHUNK * 8192];   // fragment-permuted B (tf32-rounded)
__device__ int           g_icnt[NM];
__device__ unsigned char g_ilist[NM * MAXINV];

// ---------------- helpers ----------------
__device__ __forceinline__ uint32_t smem_u32(const void* p) {
    uint32_t a;
    asm("{ .reg .u64 t; cvta.to.shared.u64 t, %1; cvt.u32.u64 %0, t; }" : "=r"(a) : "l"(p));
    return a;
}
__device__ __forceinline__ void cp16(uint32_t dst, const void* src) {
    asm volatile("cp.async.cg.shared.global [%0], [%1], 16;" :: "r"(dst), "l"(src));
}
#define CP_COMMIT() asm volatile("cp.async.commit_group;" ::: "memory")
#define CP_WAIT(N)  asm volatile("cp.async.wait_group %0;" :: "n"(N) : "memory")

// m16n8k8 tf32 MMA, D += A*B
__device__ __forceinline__ void mma_tf32(float* d, const uint32_t* a, uint32_t b0, uint32_t b1) {
    asm volatile(
        "mma.sync.aligned.m16n8k8.row.col.f32.tf32.tf32.f32 "
        "{%0,%1,%2,%3}, {%4,%5,%6,%7}, {%8,%9}, {%0,%1,%2,%3};"
        : "+f"(d[0]), "+f"(d[1]), "+f"(d[2]), "+f"(d[3])
        : "r"(a[0]), "r"(a[1]), "r"(a[2]), "r"(a[3]), "r"(b0), "r"(b1));
}

// ---------------- merged prologue kernel ----------------
// blocks 0..639: permute B into fragment order [chunk][ntile 32][kstep 4][lane 32][2]
// block 640: build inverse map (phoneme -> phone list) via ballot compaction
__global__ void prep_kernel(const float* __restrict__ f2p,
                            const float* __restrict__ mapping) {
    if (blockIdx.x < 640) {
        int idx = blockIdx.x * 256 + threadIdx.x;   // < NCHUNK*8192 = 163840
        int kc   = idx >> 13;
        int rem  = idx & 8191;
        int nt   = rem >> 8;
        int r2   = rem & 255;
        int ks   = r2 >> 6;
        int lane = (r2 >> 1) & 31;
        int i    = r2 & 1;
        int n = nt * 8 + (lane >> 2);
        int k = kc * KC + ks * 8 + (lane & 3) + 4 * i;
        float v = (n < NP) ? f2p[k * NP + n] : 0.0f;
        uint32_t t;
        asm("cvt.rna.tf32.f32 %0, %1;" : "=r"(t) : "f"(v));
        g_Bp[idx] = __uint_as_float(t);
    } else {
        int wid  = threadIdx.x >> 5;
        int lane = threadIdx.x & 31;
        for (int m = wid; m < NM; m += 8) {
            int cnt = 0;
            for (int base = 0; base < NP; base += 32) {
                int p = base + lane;
                bool hit = (p < NP) && (mapping[m * NP + p] > 0.0f);
                unsigned bal = __ballot_sync(0xffffffffu, hit);
                if (hit) {
                    int pos = cnt + __popc(bal & ((1u << lane) - 1u));
                    if (pos < MAXINV) g_ilist[m * MAXINV + pos] = (unsigned char)p;
                }
                cnt += __popc(bal);
            }
            if (lane == 0) g_icnt[m] = (cnt < MAXINV) ? cnt : MAXINV;
        }
    }
}

// ---------------- main kernel ----------------
__global__ __launch_bounds__(256, 1)
void phon_mma_kernel(const float* __restrict__ enc, float* __restrict__ out) {
    extern __shared__ char smem[];
    const uint32_t sbase = smem_u32(smem);
    const int tid  = threadIdx.x;
    const int wid  = tid >> 5;
    const int lane = tid & 31;
    const int wm   = wid >> 2;   // 0..1
    const int wn   = wid & 3;    // 0..3
    const int row0 = blockIdx.x * TM;

    int*           sicnt  = (int*)(smem + SM_TBL);
    unsigned char* silist = (unsigned char*)(smem + SM_ILIST);
    float*         sMaxv  = (float*)(smem + SM_MAXV);
    float*         sLsev  = (float*)(smem + SM_LSEV);

    // stage inverse-map tables (covered by first __syncthreads in loop)
    if (tid < NM) sicnt[tid] = g_icnt[tid];
    for (int i = tid; i < NM * MAXINV; i += 256) silist[i] = g_ilist[i];

    float acc[2][8][4];
    #pragma unroll
    for (int i = 0; i < 2; i++)
        #pragma unroll
        for (int j = 0; j < 8; j++)
            #pragma unroll
            for (int c = 0; c < 4; c++) acc[i][j][c] = 0.0f;

    auto issue_chunk = [&](int kc, int buf) {
        uint32_t adst = sbase + SM_A0 + buf * A_BYTES;
        #pragma unroll
        for (int it = 0; it < 2; it++) {
            int i4 = tid + it * 256;
            int r = i4 >> 3, g = i4 & 7;
            cp16(adst + (uint32_t)(r * A_PAD + g * 4) * 4,
                 enc + (size_t)(row0 + r) * HD + kc * KC + g * 4);
        }
        uint32_t bdst = sbase + SM_B0 + buf * B_BYTES;
        const float* bsrc = g_Bp + (size_t)kc * 8192;
        #pragma unroll
        for (int it = 0; it < 8; it++) {
            int i4 = tid + it * 256;
            cp16(bdst + (uint32_t)i4 * 16, bsrc + (size_t)i4 * 4);
        }
    };

    auto do_chunk = [&](int buf) {
        const float* sA = (const float*)(smem + SM_A0 + buf * A_BYTES);
        const char*  sB = smem + SM_B0 + buf * B_BYTES;
        #pragma unroll
        for (int ks = 0; ks < 4; ks++) {
            uint32_t afr[2][4];
            #pragma unroll
            for (int i = 0; i < 2; i++) {
                const float* ap = sA + (wm * 32 + i * 16 + (lane >> 2)) * A_PAD
                                     + ks * 8 + (lane & 3);
                afr[i][0] = __float_as_uint(ap[0]);
                afr[i][1] = __float_as_uint(ap[8 * A_PAD]);
                afr[i][2] = __float_as_uint(ap[4]);
                afr[i][3] = __float_as_uint(ap[8 * A_PAD + 4]);
            }
            float2 bfr[8];
            #pragma unroll
            for (int j = 0; j < 8; j++) {
                int nt = wn * 8 + j;
                bfr[j] = *(const float2*)(sB + ((nt * 4 + ks) * 32 + lane) * 8);
            }
            #pragma unroll
            for (int i = 0; i < 2; i++)
                #pragma unroll
                for (int j = 0; j < 8; j++)
                    mma_tf32(acc[i][j], afr[i],
                             __float_as_uint(bfr[j].x), __float_as_uint(bfr[j].y));
        }
    };

    // 3-stage pipeline: fill 2 stages
    issue_chunk(0, 0); CP_COMMIT();
    issue_chunk(1, 1); CP_COMMIT();

    #pragma unroll 1
    for (int kc = 0; kc < NCHUNK; kc++) {
        if (kc == NCHUNK - 1) { CP_WAIT(0); } else { CP_WAIT(STAGES - 2); }
        __syncthreads();   // chunk kc visible to all; buffer (kc-1)%S free for reuse
        if (kc + 2 < NCHUNK) {
            issue_chunk(kc + 2, (kc + 2) % STAGES);
            CP_COMMIT();
        }
        do_chunk(kc % STAGES);
    }
    __syncthreads();  // all compute done before aliasing GEMM buffers

    // ---- epilogue ----
    const float scale = 0.039528470752104741f;  // 1/sqrt(640)
    float* sPhone = (float*)(smem + SM_PHONE);
    float* sPh    = (float*)(smem + SM_PH);

    #pragma unroll
    for (int i = 0; i < 2; i++) {
        int r = wm * 32 + i * 16 + (lane >> 2);
        #pragma unroll
        for (int j = 0; j < 8; j++) {
            int c = wn * 64 + j * 8 + (lane & 3) * 2;
            float2 v0 = make_float2(acc[i][j][0] * scale, acc[i][j][1] * scale);
            float2 v1 = make_float2(acc[i][j][2] * scale, acc[i][j][3] * scale);
            *(float2*)(sPhone + r * P_PAD + c)       = v0;
            *(float2*)(sPhone + (r + 8) * P_PAD + c) = v1;
        }
    }
    __syncthreads();

    // gather-max via inverse map: 64 rows x 96 phonemes over 256 threads
    for (int idx = tid; idx < TM * NM; idx += 256) {
        int r = idx / NM;
        int m = idx - r * NM;
        int cnt = sicnt[m];
        const unsigned char* lst = silist + m * MAXINV;
        float mx = -INFINITY;
        for (int c = 0; c < cnt; c++)
            mx = fmaxf(mx, sPhone[r * P_PAD + lst[c]]);
        sPh[r * M_PAD + m] = mx;
    }
    __syncthreads();

    // per-row max + logsumexp: 4 threads per row, shfl reduce within 4-lane group
    {
        int r = tid >> 2;          // 0..63
        int q = tid & 3;           // quarter
        const float* row = sPh + r * M_PAD;
        float mx = -INFINITY;
        #pragma unroll
        for (int m = q * 24; m < q * 24 + 24; m++) mx = fmaxf(mx, row[m]);
        mx = fmaxf(mx, __shfl_xor_sync(0xffffffffu, mx, 1));
        mx = fmaxf(mx, __shfl_xor_sync(0xffffffffu, mx, 2));
        float s = 0.0f;
        #pragma unroll
        for (int m = q * 24; m < q * 24 + 24; m++) s += expf(row[m] - mx);
        s += __shfl_xor_sync(0xffffffffu, s, 1);
        s += __shfl_xor_sync(0xffffffffu, s, 2);
        if (q == 0) { sMaxv[r] = mx; sLsev[r] = logf(s); }
    }
    __syncthreads();

    // coalesced output
    for (int idx = tid; idx < TM * NM; idx += 256) {
        int r = idx / NM;
        int m = idx - r * NM;
        out[(size_t)(row0 + r) * NM + m] = sPh[r * M_PAD + m] - sMaxv[r] - sLsev[r];
    }
}

extern "C" void kernel_launch(void* const* d_in, const int* in_sizes, int n_in,
                              void* d_out, int out_size) {
    const float* enc     = (const float*)d_in[0];
    const float* f2p     = (const float*)d_in[1];
    const float* mapping = (const float*)d_in[2];
    float*       out     = (float*)d_out;

    cudaFuncSetAttribute(phon_mma_kernel,
                         cudaFuncAttributeMaxDynamicSharedMemorySize, SM_TOTAL);

    prep_kernel<<<641, 256>>>(f2p, mapping);
    phon_mma_kernel<<<NROWS / TM, 256, SM_TOTAL>>>(enc, out);
}

// round 7
// speedup vs baseline: 1.0719x; 1.0719x over previous
#include <cuda_runtime.h>
#include <math.h>
#include <stdint.h>

#define NROWS 8192      // B*T
#define HD    640
#define NP    230
#define NM    96
#define TM    64        // rows per CTA
#define KC    32        // k per chunk
#define NCHUNK (HD / KC)  // 20
#define A_PAD 36
#define P_PAD 258
#define M_PAD 97
#define MAXINV 32
#define NTHREADS 512

#define A_BYTES 9216    // 64*36*4
#define B_BYTES 32768   // 8192 floats

// ---- smem byte offsets ----
#define SM_A0    0                        // 2 x 9216  = 18432
#define SM_B0    18432                    // 2 x 32768 = 65536 -> 83968
// epilogue aliases GEMM region:
#define SM_PHONE 0                        // 64*258*4 = 66048
#define SM_PH    66048                    // 64*97*4  = 24832 -> 90880
// persistent tables:
#define SM_TBL   90880                    // icnt 96*4 -> 91264
#define SM_ILIST 91264                    // 96*32    -> 94336
#define SM_MAXV  94336                    // 64*4
#define SM_LSEV  94592                    // 64*4
#define SM_TOTAL 94848

__device__ float         g_Bp[NCHUNK * 8192];   // fragment-permuted B (tf32-rounded)
__device__ int           g_icnt[NM];
__device__ unsigned char g_ilist[NM * MAXINV];

// ---------------- helpers ----------------
__device__ __forceinline__ uint32_t smem_u32(const void* p) {
    uint32_t a;
    asm("{ .reg .u64 t; cvta.to.shared.u64 t, %1; cvt.u32.u64 %0, t; }" : "=r"(a) : "l"(p));
    return a;
}
__device__ __forceinline__ void cp16(uint32_t dst, const void* src) {
    asm volatile("cp.async.cg.shared.global [%0], [%1], 16;" :: "r"(dst), "l"(src));
}
#define CP_COMMIT() asm volatile("cp.async.commit_group;" ::: "memory")
#define CP_WAIT(N)  asm volatile("cp.async.wait_group %0;" :: "n"(N) : "memory")

// m16n8k8 tf32 MMA, D += A*B
__device__ __forceinline__ void mma_tf32(float* d, const uint32_t* a, uint32_t b0, uint32_t b1) {
    asm volatile(
        "mma.sync.aligned.m16n8k8.row.col.f32.tf32.tf32.f32 "
        "{%0,%1,%2,%3}, {%4,%5,%6,%7}, {%8,%9}, {%0,%1,%2,%3};"
        : "+f"(d[0]), "+f"(d[1]), "+f"(d[2]), "+f"(d[3])
        : "r"(a[0]), "r"(a[1]), "r"(a[2]), "r"(a[3]), "r"(b0), "r"(b1));
}

// ---------------- prologue kernel ----------------
// blocks 0..19: pack one 32-row chunk of B into fragment order
//   [chunk][ntile 32][kstep 4][lane 32][2] via a coalesced smem staging pass.
// block 20: build inverse map (phoneme -> phone list).
__global__ void prep_kernel(const float* __restrict__ f2p,
                            const float* __restrict__ mapping) {
    __shared__ float s[32 * 232];
    const int tid = threadIdx.x;
    const int b   = blockIdx.x;
    if (b < NCHUNK) {
        // stage 32 rows of f2p (contiguous slab, fully coalesced)
        const float* src = f2p + (size_t)b * KC * NP;
        for (int idx = tid; idx < KC * NP; idx += 256) {
            int rr = idx / NP, c = idx - rr * NP;
            s[rr * 232 + c] = src[idx];
        }
        __syncthreads();
        // permute out, coalesced writes
        float* dst = g_Bp + (size_t)b * 8192;
        for (int rem = tid; rem < 8192; rem += 256) {
            int nt   = rem >> 8;
            int r2   = rem & 255;
            int ks   = r2 >> 6;
            int lane = (r2 >> 1) & 31;
            int i    = r2 & 1;
            int n  = nt * 8 + (lane >> 2);
            int kk = ks * 8 + (lane & 3) + 4 * i;
            float v = (n < NP) ? s[kk * 232 + n] : 0.0f;
            uint32_t t;
            asm("cvt.rna.tf32.f32 %0, %1;" : "=r"(t) : "f"(v));
            dst[rem] = __uint_as_float(t);
        }
    } else {
        int wid  = tid >> 5;
        int lane = tid & 31;
        for (int m = wid; m < NM; m += 8) {
            int cnt = 0;
            for (int base = 0; base < NP; base += 32) {
                int p = base + lane;
                bool hit = (p < NP) && (mapping[m * NP + p] > 0.0f);
                unsigned bal = __ballot_sync(0xffffffffu, hit);
                if (hit) {
                    int pos = cnt + __popc(bal & ((1u << lane) - 1u));
                    if (pos < MAXINV) g_ilist[m * MAXINV + pos] = (unsigned char)p;
                }
                cnt += __popc(bal);
            }
            if (lane == 0) g_icnt[m] = (cnt < MAXINV) ? cnt : MAXINV;
        }
    }
}

// ---------------- main kernel ----------------
__global__ __launch_bounds__(NTHREADS, 1)
void phon_mma_kernel(const float* __restrict__ enc, float* __restrict__ out) {
    extern __shared__ char smem[];
    const uint32_t sbase = smem_u32(smem);
    const int tid  = threadIdx.x;
    const int wid  = tid >> 5;
    const int lane = tid & 31;
    const int wm   = wid >> 3;   // 0..1  (M half)
    const int wn   = wid & 7;    // 0..7  (32-col slice)
    const int row0 = blockIdx.x * TM;

    int*           sicnt  = (int*)(smem + SM_TBL);
    unsigned char* silist = (unsigned char*)(smem + SM_ILIST);
    float*         sMaxv  = (float*)(smem + SM_MAXV);
    float*         sLsev  = (float*)(smem + SM_LSEV);

    // stage inverse-map tables (covered by first __syncthreads)
    if (tid < NM) sicnt[tid] = g_icnt[tid];
    for (int i = tid; i < NM * MAXINV; i += NTHREADS) silist[i] = g_ilist[i];

    float acc[2][4][4];
    #pragma unroll
    for (int i = 0; i < 2; i++)
        #pragma unroll
        for (int j = 0; j < 4; j++)
            #pragma unroll
            for (int c = 0; c < 4; c++) acc[i][j][c] = 0.0f;

    auto issue_chunk = [&](int kc, int buf) {
        // A: 64 rows x 32 floats = 512 float4, one per thread
        {
            int r = tid >> 3, g = tid & 7;
            cp16(sbase + SM_A0 + buf * A_BYTES + (uint32_t)(r * A_PAD + g * 4) * 4,
                 enc + (size_t)(row0 + r) * HD + kc * KC + g * 4);
        }
        // B: 8192 floats = 2048 float4, 4 per thread, contiguous
        uint32_t bdst = sbase + SM_B0 + buf * B_BYTES;
        const float* bsrc = g_Bp + (size_t)kc * 8192;
        #pragma unroll
        for (int it = 0; it < 4; it++) {
            int i4 = tid + it * NTHREADS;
            cp16(bdst + (uint32_t)i4 * 16, bsrc + (size_t)i4 * 4);
        }
    };

    auto do_chunk = [&](int buf) {
        const float* sA = (const float*)(smem + SM_A0 + buf * A_BYTES);
        const char*  sB = smem + SM_B0 + buf * B_BYTES;
        #pragma unroll
        for (int ks = 0; ks < 4; ks++) {
            uint32_t afr[2][4];
            #pragma unroll
            for (int i = 0; i < 2; i++) {
                const float* ap = sA + (wm * 32 + i * 16 + (lane >> 2)) * A_PAD
                                     + ks * 8 + (lane & 3);
                afr[i][0] = __float_as_uint(ap[0]);
                afr[i][1] = __float_as_uint(ap[8 * A_PAD]);
                afr[i][2] = __float_as_uint(ap[4]);
                afr[i][3] = __float_as_uint(ap[8 * A_PAD + 4]);
            }
            float2 bfr[4];
            #pragma unroll
            for (int j = 0; j < 4; j++) {
                int nt = wn * 4 + j;
                bfr[j] = *(const float2*)(sB + ((nt * 4 + ks) * 32 + lane) * 8);
            }
            #pragma unroll
            for (int i = 0; i < 2; i++)
                #pragma unroll
                for (int j = 0; j < 4; j++)
                    mma_tf32(acc[i][j], afr[i],
                             __float_as_uint(bfr[j].x), __float_as_uint(bfr[j].y));
        }
    };

    issue_chunk(0, 0);
    CP_COMMIT();
    #pragma unroll 1
    for (int kc = 0; kc < NCHUNK; kc++) {
        if (kc + 1 < NCHUNK) {
            issue_chunk(kc + 1, (kc + 1) & 1);
            CP_COMMIT();
            CP_WAIT(1);
        } else {
            CP_WAIT(0);
        }
        __syncthreads();
        do_chunk(kc & 1);
        __syncthreads();
    }

    // ---- epilogue ----
    const float scale = 0.039528470752104741f;  // 1/sqrt(640)
    float* sPhone = (float*)(smem + SM_PHONE);
    float* sPh    = (float*)(smem + SM_PH);

    #pragma unroll
    for (int i = 0; i < 2; i++) {
        int r = wm * 32 + i * 16 + (lane >> 2);
        #pragma unroll
        for (int j = 0; j < 4; j++) {
            int c = wn * 32 + j * 8 + (lane & 3) * 2;
            float2 v0 = make_float2(acc[i][j][0] * scale, acc[i][j][1] * scale);
            float2 v1 = make_float2(acc[i][j][2] * scale, acc[i][j][3] * scale);
            *(float2*)(sPhone + r * P_PAD + c)       = v0;
            *(float2*)(sPhone + (r + 8) * P_PAD + c) = v1;
        }
    }
    __syncthreads();

    // gather-max via inverse map: 64 rows x 96 phonemes
    for (int idx = tid; idx < TM * NM; idx += NTHREADS) {
        int r = idx / NM;
        int m = idx - r * NM;
        int cnt = sicnt[m];
        const unsigned char* lst = silist + m * MAXINV;
        float mx = -INFINITY;
        for (int c = 0; c < cnt; c++)
            mx = fmaxf(mx, sPhone[r * P_PAD + lst[c]]);
        sPh[r * M_PAD + m] = mx;
    }
    __syncthreads();

    // per-row max + logsumexp: 4 threads per row (first 256 threads)
    if (tid < 256) {
        int r = tid >> 2;
        int q = tid & 3;
        const float* row = sPh + r * M_PAD;
        float mx = -INFINITY;
        #pragma unroll
        for (int m = q * 24; m < q * 24 + 24; m++) mx = fmaxf(mx, row[m]);
        mx = fmaxf(mx, __shfl_xor_sync(0xffffffffu, mx, 1));
        mx = fmaxf(mx, __shfl_xor_sync(0xffffffffu, mx, 2));
        float s = 0.0f;
        #pragma unroll
        for (int m = q * 24; m < q * 24 + 24; m++) s += expf(row[m] - mx);
        s += __shfl_xor_sync(0xffffffffu, s, 1);
        s += __shfl_xor_sync(0xffffffffu, s, 2);
        if (q == 0) { sMaxv[r] = mx; sLsev[r] = logf(s); }
    }
    __syncthreads();

    // coalesced output
    for (int idx = tid; idx < TM * NM; idx += NTHREADS) {
        int r = idx / NM;
        int m = idx - r * NM;
        out[(size_t)(row0 + r) * NM + m] = sPh[r * M_PAD + m] - sMaxv[r] - sLsev[r];
    }
}

extern "C" void kernel_launch(void* const* d_in, const int* in_sizes, int n_in,
                              void* d_out, int out_size) {
    const float* enc     = (const float*)d_in[0];
    const float* f2p     = (const float*)d_in[1];
    const float* mapping = (const float*)d_in[2];
    float*       out     = (float*)d_out;

    cudaFuncSetAttribute(phon_mma_kernel,
                         cudaFuncAttributeMaxDynamicSharedMemorySize, SM_TOTAL);

    prep_kernel<<<NCHUNK + 1, 256>>>(f2p, mapping);
    phon_mma_kernel<<<NROWS / TM, NTHREADS, SM_TOTAL>>>(enc, out);
}